// round 14
// baseline (speedup 1.0000x reference)
#include <cuda_runtime.h>
#include <cstdint>
#include <cstddef>

// Problem constants (fixed by the reference: B=64, T=512, S=16, NZ=512)
#define BB 64
#define TT 512
#define SS 16
#define NZ 512

// Output layout (float32, concatenated flattened reference outputs):
//   cell_input      : [B, T, NZ]     at offset 0
//   reset_input     : [B, T, 2*NZ]   at offset B*T*NZ
//   reset_indicator : [B, T]         at offset B*T*3*NZ   (written as 0.0f / 1.0f)

// 256-bit global load (sm_100a): 8 consecutive f32, 32B-aligned.
__device__ __forceinline__ void ldg_v8(const float* __restrict__ p, float* v) {
    uint32_t r0, r1, r2, r3, r4, r5, r6, r7;
    asm volatile("ld.global.nc.v8.b32 {%0,%1,%2,%3,%4,%5,%6,%7}, [%8];"
                 : "=r"(r0), "=r"(r1), "=r"(r2), "=r"(r3),
                   "=r"(r4), "=r"(r5), "=r"(r6), "=r"(r7)
                 : "l"(p));
    v[0] = __uint_as_float(r0); v[1] = __uint_as_float(r1);
    v[2] = __uint_as_float(r2); v[3] = __uint_as_float(r3);
    v[4] = __uint_as_float(r4); v[5] = __uint_as_float(r5);
    v[6] = __uint_as_float(r6); v[7] = __uint_as_float(r7);
}

// 256-bit global store (sm_100a): 8 consecutive f32, 32B-aligned.
__device__ __forceinline__ void stg_v8(float* __restrict__ p, const float* v) {
    asm volatile("st.global.v8.b32 [%0], {%1,%2,%3,%4,%5,%6,%7,%8};"
                 :: "l"(p),
                    "r"(__float_as_uint(v[0])), "r"(__float_as_uint(v[1])),
                    "r"(__float_as_uint(v[2])), "r"(__float_as_uint(v[3])),
                    "r"(__float_as_uint(v[4])), "r"(__float_as_uint(v[5])),
                    "r"(__float_as_uint(v[6])), "r"(__float_as_uint(v[7]))
                 : "memory");
}

__global__ __launch_bounds__(128, 12)
void soft2frames_kernel(const float* __restrict__ seg_start,  // [S, B]
                        const float* __restrict__ seg_end,    // [S, B]
                        const float* __restrict__ e0_seg,     // [S, B, NZ]
                        const float* __restrict__ eg_seg,     // [S, B, NZ]
                        float* __restrict__ out) {
    const int t   = blockIdx.x;   // 0..T-1
    const int b   = blockIdx.y;   // 0..B-1
    const int tid = threadIdx.x;  // 0..127

    __shared__ int   sh_sel;
    __shared__ int   sh_ind;
    __shared__ float sh_inter;

    // ---- segment selection: one warp, one lane per segment (identical to champion) ----
    if (tid < 32) {
        float ss = 0.f, se = 0.f;
        int inr = 0, hit = 0;
        if (tid < SS) {
            ss = __ldg(&seg_start[tid * BB + b]);
            se = __ldg(&seg_end[tid * BB + b]);
            const int cs = (int)ceilf(ss);
            const int fe = (int)floorf(se);
            inr = (t >= cs) & (t <= fe);
            hit = (min(max(cs, 0), TT - 1) == t);
        }
        const unsigned mc = __ballot_sync(0xffffffffu, inr);
        const unsigned mi = __ballot_sync(0xffffffffu, hit);
        const int sel = 31 - __clz(mc);            // last segment wins; -1 if uncovered
        const float st = __shfl_sync(0xffffffffu, ss, sel & 31);
        const float en = __shfl_sync(0xffffffffu, se, sel & 31);
        if (tid == 0) {
            sh_sel   = sel;
            sh_ind   = (mi != 0u);
            sh_inter = ((float)t - st) / (en - st + 1e-7f);
        }
    }
    __syncthreads();

    const int   sel   = sh_sel;
    const float inter = sh_inter;

    const size_t bt = (size_t)b * TT + t;
    float* __restrict__ cell_row = out + bt * NZ;
    float* __restrict__ rst_row  = out + (size_t)BB * TT * NZ + bt * (2 * NZ);

    // Thread c owns 32B chunk c of reset: c<64 -> g-half, c>=64 -> e-half.
    const int  eo   = (tid & 63) * 8;   // float offset within the NZ row
    const bool is_g = (tid < 64);

    if (sel >= 0) {
        const size_t base = ((size_t)sel * BB + b) * NZ;
        float r[8];
        ldg_v8((is_g ? eg_seg : e0_seg) + base + eo, r);
        stg_v8(rst_row + tid * 8, r);            // reset_input = [g | e]

        if (is_g) {                              // threads 0..63: also produce cell chunk
            float e8[8];
            ldg_v8(e0_seg + base + eo, e8);      // L1 hit (lines fetched by warps 2-3)
            float c8[8];
#pragma unroll
            for (int i = 0; i < 8; ++i)
                c8[i] = fmaf(r[i] - e8[i], inter, e8[i]);
            stg_v8(cell_row + eo, c8);           // cell_input
        }
    } else {
        const float z8[8] = {0.f, 0.f, 0.f, 0.f, 0.f, 0.f, 0.f, 0.f};
        stg_v8(rst_row + tid * 8, z8);
        if (is_g) stg_v8(cell_row + eo, z8);
    }

    if (tid == 0) {
        out[(size_t)BB * TT * 3 * NZ + bt] = (float)sh_ind;  // reset_indicator
    }
}

extern "C" void kernel_launch(void* const* d_in, const int* in_sizes, int n_in,
                              void* d_out, int out_size) {
    const float* seg_start = (const float*)d_in[0];
    const float* seg_end   = (const float*)d_in[1];
    const float* e0_seg    = (const float*)d_in[2];
    const float* eg_seg    = (const float*)d_in[3];
    float* out = (float*)d_out;

    dim3 grid(TT, BB);
    soft2frames_kernel<<<grid, 128>>>(seg_start, seg_end, e0_seg, eg_seg, out);
}

// round 15
// speedup vs baseline: 1.0632x; 1.0632x over previous
#include <cuda_runtime.h>
#include <cstddef>

// Problem constants (fixed by the reference: B=64, T=512, S=16, NZ=512)
#define BB 64
#define TT 512
#define SS 16
#define NZ 512

// Output layout (float32, concatenated flattened reference outputs):
//   cell_input      : [B, T, NZ]     at offset 0
//   reset_input     : [B, T, 2*NZ]   at offset B*T*NZ
//   reset_indicator : [B, T]         at offset B*T*3*NZ   (written as 0.0f / 1.0f)

__global__ __launch_bounds__(NZ / 4, 12)
void soft2frames_kernel(const float* __restrict__ seg_start,  // [S, B]
                        const float* __restrict__ seg_end,    // [S, B]
                        const float* __restrict__ e0_seg,     // [S, B, NZ]
                        const float* __restrict__ eg_seg,     // [S, B, NZ]
                        float* __restrict__ out) {
    const int t   = blockIdx.x;   // 0..T-1
    const int b   = blockIdx.y;   // 0..B-1
    const int tid = threadIdx.x;  // 0..127, one float4 lane of NZ

    __shared__ int   sh_sel;
    __shared__ int   sh_ind;
    __shared__ float sh_inter;

    // ---- segment selection: one warp, one lane per segment ----
    if (tid < 32) {
        float ss = 0.f, se = 0.f;
        int inr = 0, hit = 0;
        if (tid < SS) {
            ss = __ldg(&seg_start[tid * BB + b]);
            se = __ldg(&seg_end[tid * BB + b]);
            const int cs = (int)ceilf(ss);
            const int fe = (int)floorf(se);
            inr = (t >= cs) & (t <= fe);
            hit = (min(max(cs, 0), TT - 1) == t);
        }
        const unsigned mc = __ballot_sync(0xffffffffu, inr);
        const unsigned mi = __ballot_sync(0xffffffffu, hit);
        const int sel = 31 - __clz(mc);            // last segment wins; -1 if uncovered
        const float st = __shfl_sync(0xffffffffu, ss, sel & 31);
        const float en = __shfl_sync(0xffffffffu, se, sel & 31);
        if (tid == 0) {
            sh_sel   = sel;
            sh_ind   = (mi != 0u);
            sh_inter = ((float)t - st) / (en - st + 1e-7f);
        }
    }
    __syncthreads();

    const int   sel   = sh_sel;
    const float inter = sh_inter;

    const size_t bt = (size_t)b * TT + t;
    float* __restrict__ cellp = out + bt * NZ + tid * 4;
    float* __restrict__ rstp  = out + (size_t)BB * TT * NZ + bt * (2 * NZ) + tid * 4;

    if (sel >= 0) {
        const size_t base = ((size_t)sel * BB + b) * NZ;
        const float4 e = __ldg((const float4*)(e0_seg + base) + tid);
        const float4 g = __ldg((const float4*)(eg_seg + base) + tid);
        float4 c;
        c.x = fmaf(g.x - e.x, inter, e.x);
        c.y = fmaf(g.y - e.y, inter, e.y);
        c.z = fmaf(g.z - e.z, inter, e.z);
        c.w = fmaf(g.w - e.w, inter, e.w);
        __stcs((float4*)cellp, c);            // cell_input
        __stcs((float4*)rstp, g);             // reset_input[:, :NZ]  = e_gs
        __stcs((float4*)(rstp + NZ), e);      // reset_input[:, NZ:]  = e_0s
    } else {
        const float4 z = make_float4(0.f, 0.f, 0.f, 0.f);
        __stcs((float4*)cellp, z);
        __stcs((float4*)rstp, z);
        __stcs((float4*)(rstp + NZ), z);
    }

    if (tid == 0) {
        __stcs(out + (size_t)BB * TT * 3 * NZ + bt, (float)sh_ind);  // reset_indicator
    }
}

extern "C" void kernel_launch(void* const* d_in, const int* in_sizes, int n_in,
                              void* d_out, int out_size) {
    const float* seg_start = (const float*)d_in[0];
    const float* seg_end   = (const float*)d_in[1];
    const float* e0_seg    = (const float*)d_in[2];
    const float* eg_seg    = (const float*)d_in[3];
    float* out = (float*)d_out;

    dim3 grid(TT, BB);
    soft2frames_kernel<<<grid, NZ / 4>>>(seg_start, seg_end, e0_seg, eg_seg, out);
}

// round 16
// speedup vs baseline: 1.0700x; 1.0065x over previous
#include <cuda_runtime.h>
#include <cstddef>

// Problem constants (fixed by the reference: B=64, T=512, S=16, NZ=512)
#define BB 64
#define TT 512
#define SS 16
#define NZ 512

// Output layout (float32, concatenated flattened reference outputs):
//   cell_input      : [B, T, NZ]     at offset 0
//   reset_input     : [B, T, 2*NZ]   at offset B*T*NZ
//   reset_indicator : [B, T]         at offset B*T*3*NZ   (written as 0.0f / 1.0f)
//
// Final champion (5x reproduced at 34.75-34.94 us e2e):
//  - one warp does segment selection via ballot/clz (last-match-wins), SMEM broadcast
//  - __syncthreads releases all 4 warps' store streams together (dense write waves)
//  - 128 threads x float4 fully-coalesced STG.128 streams; evict-first hint
//  - kernel sits at the measured HBM write floor: ~146 MB DRAM/replay @ ~4.1 TB/s

__global__ __launch_bounds__(NZ / 4, 12)
void soft2frames_kernel(const float* __restrict__ seg_start,  // [S, B]
                        const float* __restrict__ seg_end,    // [S, B]
                        const float* __restrict__ e0_seg,     // [S, B, NZ]
                        const float* __restrict__ eg_seg,     // [S, B, NZ]
                        float* __restrict__ out) {
    const int t   = blockIdx.x;   // 0..T-1
    const int b   = blockIdx.y;   // 0..B-1
    const int tid = threadIdx.x;  // 0..127, one float4 lane of NZ

    __shared__ int   sh_sel;
    __shared__ int   sh_ind;
    __shared__ float sh_inter;

    // ---- segment selection: one warp, one lane per segment ----
    if (tid < 32) {
        float ss = 0.f, se = 0.f;
        int inr = 0, hit = 0;
        if (tid < SS) {
            ss = __ldg(&seg_start[tid * BB + b]);
            se = __ldg(&seg_end[tid * BB + b]);
            const int cs = (int)ceilf(ss);
            const int fe = (int)floorf(se);
            inr = (t >= cs) & (t <= fe);
            hit = (min(max(cs, 0), TT - 1) == t);
        }
        const unsigned mc = __ballot_sync(0xffffffffu, inr);
        const unsigned mi = __ballot_sync(0xffffffffu, hit);
        const int sel = 31 - __clz(mc);            // last segment wins; -1 if uncovered
        const float st = __shfl_sync(0xffffffffu, ss, sel & 31);
        const float en = __shfl_sync(0xffffffffu, se, sel & 31);
        if (tid == 0) {
            sh_sel   = sel;
            sh_ind   = (mi != 0u);
            sh_inter = ((float)t - st) / (en - st + 1e-7f);
        }
    }
    __syncthreads();

    const int   sel   = sh_sel;
    const float inter = sh_inter;

    const size_t bt = (size_t)b * TT + t;
    float* __restrict__ cellp = out + bt * NZ + tid * 4;
    float* __restrict__ rstp  = out + (size_t)BB * TT * NZ + bt * (2 * NZ) + tid * 4;

    if (sel >= 0) {
        const size_t base = ((size_t)sel * BB + b) * NZ;
        const float4 e = __ldg((const float4*)(e0_seg + base) + tid);
        const float4 g = __ldg((const float4*)(eg_seg + base) + tid);
        float4 c;
        c.x = fmaf(g.x - e.x, inter, e.x);
        c.y = fmaf(g.y - e.y, inter, e.y);
        c.z = fmaf(g.z - e.z, inter, e.z);
        c.w = fmaf(g.w - e.w, inter, e.w);
        __stcs((float4*)cellp, c);            // cell_input
        __stcs((float4*)rstp, g);             // reset_input[:, :NZ]  = e_gs
        __stcs((float4*)(rstp + NZ), e);      // reset_input[:, NZ:]  = e_0s
    } else {
        const float4 z = make_float4(0.f, 0.f, 0.f, 0.f);
        __stcs((float4*)cellp, z);
        __stcs((float4*)rstp, z);
        __stcs((float4*)(rstp + NZ), z);
    }

    if (tid == 0) {
        __stcs(out + (size_t)BB * TT * 3 * NZ + bt, (float)sh_ind);  // reset_indicator
    }
}

extern "C" void kernel_launch(void* const* d_in, const int* in_sizes, int n_in,
                              void* d_out, int out_size) {
    const float* seg_start = (const float*)d_in[0];
    const float* seg_end   = (const float*)d_in[1];
    const float* e0_seg    = (const float*)d_in[2];
    const float* eg_seg    = (const float*)d_in[3];
    float* out = (float*)d_out;

    dim3 grid(TT, BB);
    soft2frames_kernel<<<grid, NZ / 4>>>(seg_start, seg_end, e0_seg, eg_seg, out);
}

// round 17
// speedup vs baseline: 1.0740x; 1.0037x over previous
#include <cuda_runtime.h>
#include <cstddef>

// Problem constants (fixed by the reference: B=64, T=512, S=16, NZ=512)
#define BB 64
#define TT 512
#define SS 16
#define NZ 512

// Output layout (float32, concatenated flattened reference outputs):
//   cell_input      : [B, T, NZ]     at offset 0
//   reset_input     : [B, T, 2*NZ]   at offset B*T*NZ
//   reset_indicator : [B, T]         at offset B*T*3*NZ   (written as 0.0f / 1.0f)
//
// Final champion (6x reproduced at 34.72-34.94 us e2e, rel_err 3.8e-8):
//  - one warp does segment selection via ballot/clz (last-match-wins), SMEM broadcast
//  - __syncthreads releases all 4 warps' store streams together (dense write waves)
//  - 128 threads x float4 fully-coalesced STG.128 streams; evict-first hint
//  - kernel sits at the measured HBM write floor: ~146 MB DRAM/replay @ ~4.1 TB/s
//  - rejected with measurements: t-chunk reg caching, TMA bulk stores, barrier-free
//    per-warp selection, default store policy, 2-t block fusion, v8 256-bit ld/st

__global__ __launch_bounds__(NZ / 4, 12)
void soft2frames_kernel(const float* __restrict__ seg_start,  // [S, B]
                        const float* __restrict__ seg_end,    // [S, B]
                        const float* __restrict__ e0_seg,     // [S, B, NZ]
                        const float* __restrict__ eg_seg,     // [S, B, NZ]
                        float* __restrict__ out) {
    const int t   = blockIdx.x;   // 0..T-1
    const int b   = blockIdx.y;   // 0..B-1
    const int tid = threadIdx.x;  // 0..127, one float4 lane of NZ

    __shared__ int   sh_sel;
    __shared__ int   sh_ind;
    __shared__ float sh_inter;

    // ---- segment selection: one warp, one lane per segment ----
    if (tid < 32) {
        float ss = 0.f, se = 0.f;
        int inr = 0, hit = 0;
        if (tid < SS) {
            ss = __ldg(&seg_start[tid * BB + b]);
            se = __ldg(&seg_end[tid * BB + b]);
            const int cs = (int)ceilf(ss);
            const int fe = (int)floorf(se);
            inr = (t >= cs) & (t <= fe);
            hit = (min(max(cs, 0), TT - 1) == t);
        }
        const unsigned mc = __ballot_sync(0xffffffffu, inr);
        const unsigned mi = __ballot_sync(0xffffffffu, hit);
        const int sel = 31 - __clz(mc);            // last segment wins; -1 if uncovered
        const float st = __shfl_sync(0xffffffffu, ss, sel & 31);
        const float en = __shfl_sync(0xffffffffu, se, sel & 31);
        if (tid == 0) {
            sh_sel   = sel;
            sh_ind   = (mi != 0u);
            sh_inter = ((float)t - st) / (en - st + 1e-7f);
        }
    }
    __syncthreads();

    const int   sel   = sh_sel;
    const float inter = sh_inter;

    const size_t bt = (size_t)b * TT + t;
    float* __restrict__ cellp = out + bt * NZ + tid * 4;
    float* __restrict__ rstp  = out + (size_t)BB * TT * NZ + bt * (2 * NZ) + tid * 4;

    if (sel >= 0) {
        const size_t base = ((size_t)sel * BB + b) * NZ;
        const float4 e = __ldg((const float4*)(e0_seg + base) + tid);
        const float4 g = __ldg((const float4*)(eg_seg + base) + tid);
        float4 c;
        c.x = fmaf(g.x - e.x, inter, e.x);
        c.y = fmaf(g.y - e.y, inter, e.y);
        c.z = fmaf(g.z - e.z, inter, e.z);
        c.w = fmaf(g.w - e.w, inter, e.w);
        __stcs((float4*)cellp, c);            // cell_input
        __stcs((float4*)rstp, g);             // reset_input[:, :NZ]  = e_gs
        __stcs((float4*)(rstp + NZ), e);      // reset_input[:, NZ:]  = e_0s
    } else {
        const float4 z = make_float4(0.f, 0.f, 0.f, 0.f);
        __stcs((float4*)cellp, z);
        __stcs((float4*)rstp, z);
        __stcs((float4*)(rstp + NZ), z);
    }

    if (tid == 0) {
        __stcs(out + (size_t)BB * TT * 3 * NZ + bt, (float)sh_ind);  // reset_indicator
    }
}

extern "C" void kernel_launch(void* const* d_in, const int* in_sizes, int n_in,
                              void* d_out, int out_size) {
    const float* seg_start = (const float*)d_in[0];
    const float* seg_end   = (const float*)d_in[1];
    const float* e0_seg    = (const float*)d_in[2];
    const float* eg_seg    = (const float*)d_in[3];
    float* out = (float*)d_out;

    dim3 grid(TT, BB);
    soft2frames_kernel<<<grid, NZ / 4>>>(seg_start, seg_end, e0_seg, eg_seg, out);
}